// round 7
// baseline (speedup 1.0000x reference)
#include <cuda_runtime.h>
#include <cstdint>
#include <math.h>

#define Nn 8
#define Cc 64
#define Hh 256
#define Ww 256
#define HW (Hh*Ww)
#define PTS 8192

// NHWC-transposed copy of x2 (scratch; __device__ global per allocation rules)
__device__ float g_x2t[(size_t)Nn * HW * Cc];

// ---------------------------------------------------------------------------
// Kernel A: fused (1) NCHW -> NHWC transpose of x2 into g_x2t and
//           (2) out = (1 + alpha) * x1 elementwise baseline.
// ---------------------------------------------------------------------------
__global__ __launch_bounds__(256) void prep_kernel(
    const float* __restrict__ x1, const float* __restrict__ x2,
    const float* __restrict__ alpha, float* __restrict__ out)
{
    __shared__ float tile[32][33];
    const int n   = blockIdx.z;
    const int c0  = blockIdx.y * 32;
    const int hw0 = blockIdx.x * 32;
    const float a1 = 1.0f + alpha[0];
    const int tx = threadIdx.x, ty = threadIdx.y;
    const size_t base = (size_t)n * Cc * HW;

    #pragma unroll
    for (int j = ty; j < 32; j += 8) {
        size_t idx = base + (size_t)(c0 + j) * HW + (size_t)(hw0 + tx);
        tile[j][tx] = x2[idx];
        out[idx] = a1 * x1[idx];
    }
    __syncthreads();

    float* pt = g_x2t + (size_t)n * HW * Cc;
    #pragma unroll
    for (int j = ty; j < 32; j += 8) {
        pt[(size_t)(hw0 + j) * Cc + (size_t)(c0 + tx)] = tile[tx][j];
    }
}

// reflect-pad index map for j = p + d - 2 in [-2, H+1]
__device__ __forceinline__ int refl(int j) {
    j = (j < 0) ? -j : j;
    return (j >= Hh) ? (2 * (Hh - 1) - j) : j;
}

// ---------------------------------------------------------------------------
// Kernel B: one block (64 threads, thread = channel) per sampled point.
// Duplicate points write identical values -> benign race.
// ---------------------------------------------------------------------------
__global__ __launch_bounds__(64) void attn_kernel(
    const float* __restrict__ x1, const int* __restrict__ SFL,
    const float* __restrict__ alpha, float* __restrict__ out)
{
    __shared__ float xa[25][Cc + 1];   // stride 65 -> conflict-free
    __shared__ float xp_s[Cc];
    __shared__ float attn_s[25];

    const int p = blockIdx.x;
    const int n = p / PTS;
    const int c = threadIdx.x;
    const int ph = SFL[2 * p];
    const int pw = SFL[2 * p + 1];

    const float xp = x1[(((size_t)n * Cc + c) * Hh + ph) * Ww + pw];
    xp_s[c] = xp;

    const float* __restrict__ xt = g_x2t + (size_t)n * HW * Cc;
    #pragma unroll
    for (int k = 0; k < 25; k++) {
        const int hj = refl(ph + k / 5 - 2);
        const int wj = refl(pw + k % 5 - 2);
        xa[k][c] = xt[((size_t)hj * Ww + wj) * Cc + c];
    }
    __syncthreads();

    if (threadIdx.x < 32) {
        const int k = threadIdx.x;
        float e = -1e30f;
        if (k < 25) {
            e = 0.0f;
            #pragma unroll 8
            for (int i = 0; i < Cc; i++)
                e += xp_s[i] * xa[k][i];
        }
        float m = e;
        #pragma unroll
        for (int o = 16; o > 0; o >>= 1)
            m = fmaxf(m, __shfl_xor_sync(0xffffffffu, m, o));
        float ex = (k < 25) ? expf(e - m) : 0.0f;
        float s = ex;
        #pragma unroll
        for (int o = 16; o > 0; o >>= 1)
            s += __shfl_xor_sync(0xffffffffu, s, o);
        if (k < 25) attn_s[k] = ex / s;
    }
    __syncthreads();

    float f = 0.0f;
    #pragma unroll
    for (int k = 0; k < 25; k++)
        f += attn_s[k] * xa[k][c];

    out[(((size_t)n * Cc + c) * Hh + ph) * Ww + pw] = xp + alpha[0] * f;
}

// ---------------------------------------------------------------------------
// Kernel C: SFL passthrough into the tail of the output buffer, CONVERTED to
// the output dtype (float32). Writing raw int bits reads as denormals ~0 when
// the harness interprets d_out as float -> rel_err 1.0. int32 values 0..255
// are exactly representable in float.
// ---------------------------------------------------------------------------
__global__ void sfl_copy_kernel(const int* __restrict__ SFL,
                                float* __restrict__ dst, int n_elems)
{
    int i = blockIdx.x * blockDim.x + threadIdx.x;
    if (i < n_elems) dst[i] = (float)SFL[i];
}

extern "C" void kernel_launch(void* const* d_in, const int* in_sizes, int n_in,
                              void* d_out, int out_size)
{
    const float* x1    = (const float*)d_in[0];
    const float* x2    = (const float*)d_in[1];
    const int*   SFL   = (const int*)d_in[2];
    const float* alpha = (const float*)d_in[3];
    float* out = (float*)d_out;

    dim3 gA(HW / 32, Cc / 32, Nn);
    prep_kernel<<<gA, dim3(32, 8)>>>(x1, x2, alpha, out);
    attn_kernel<<<Nn * PTS, 64>>>(x1, SFL, alpha, out);

    // Second tuple output: SFL as float32 at the tail of the out buffer.
    const int nsfl = in_sizes[2];                 // Nn*PTS*2 elements
    float* dst = out + ((size_t)out_size - (size_t)nsfl);
    sfl_copy_kernel<<<(nsfl + 255) / 256, 256>>>(SFL, dst, nsfl);
}

// round 9
// speedup vs baseline: 1.3266x; 1.3266x over previous
#include <cuda_runtime.h>
#include <cstdint>
#include <math.h>

#define Nn 8
#define Cc 64
#define Hh 256
#define Ww 256
#define HW (Hh*Ww)
#define PTS 8192

// NHWC-transposed copy of x2 (scratch; __device__ global per allocation rules)
__device__ float g_x2t[(size_t)Nn * HW * Cc];

// ---------------------------------------------------------------------------
// Kernel A: fused NCHW->NHWC transpose of x2 + out = (1+alpha)*x1, all float4.
// Tile: 32 channels x 128 hw positions. 256 threads.
// ---------------------------------------------------------------------------
__global__ __launch_bounds__(256) void prep_kernel(
    const float4* __restrict__ x1, const float4* __restrict__ x2,
    const float* __restrict__ alpha, float4* __restrict__ out)
{
    __shared__ float tile[32][129];   // pad 1 -> conflict-free column reads
    const int n   = blockIdx.z;
    const int c0  = blockIdx.y * 32;
    const int hw0 = blockIdx.x * 128;
    const float a1 = 1.0f + alpha[0];
    const int t = threadIdx.x;
    const int u = t & 7;          // float4 slot within row segment
    const int j = t >> 3;         // channel row 0..31
    const size_t base4 = (size_t)n * Cc * (HW / 4);

    #pragma unroll
    for (int m = 0; m < 4; m++) {
        int f4i = m * 8 + u;      // float4 index 0..31 within 128-wide row
        size_t idx = base4 + (size_t)(c0 + j) * (HW / 4) + (hw0 >> 2) + f4i;
        float4 v2 = x2[idx];
        float4 v1 = x1[idx];
        out[idx] = make_float4(a1 * v1.x, a1 * v1.y, a1 * v1.z, a1 * v1.w);
        tile[j][f4i * 4 + 0] = v2.x;
        tile[j][f4i * 4 + 1] = v2.y;
        tile[j][f4i * 4 + 2] = v2.z;
        tile[j][f4i * 4 + 3] = v2.w;
    }
    __syncthreads();

    float4* pt = (float4*)(g_x2t + (size_t)n * HW * Cc);
    #pragma unroll
    for (int v = 0; v < 4; v++) {
        int i = v * 32 + (t >> 3);    // pixel 0..127
        float4 o;
        o.x = tile[4 * u + 0][i];
        o.y = tile[4 * u + 1][i];
        o.z = tile[4 * u + 2][i];
        o.w = tile[4 * u + 3][i];
        pt[(size_t)(hw0 + i) * (Cc / 4) + (c0 >> 2) + u] = o;
    }
}

// reflect-pad index map for j = p + d - 2 in [-2, H+1]
__device__ __forceinline__ int refl(int j) {
    j = (j < 0) ? -j : j;
    return (j >= Hh) ? (2 * (Hh - 1) - j) : j;
}

// ---------------------------------------------------------------------------
// Kernel B: warp-per-point, register-resident attention. 256 thr = 8 points.
// Lane layout: half h = l>>4 owns pixels k = 2r+h (r=0..12);
//              channel group cg = 4*(l&15) (float4).
// No shared memory, no __syncthreads. Duplicate points -> identical writes.
// ---------------------------------------------------------------------------
__global__ __launch_bounds__(256) void attn_kernel(
    const float* __restrict__ x1, const int2* __restrict__ SFL,
    const float* __restrict__ alpha, float* __restrict__ out)
{
    const int p = blockIdx.x * 8 + (threadIdx.x >> 5);
    const int l = threadIdx.x & 31;
    const int n = p / PTS;
    const int2 sf = SFL[p];
    const int ph = sf.x, pw = sf.y;
    const int h  = l >> 4;
    const int cg = (l & 15) * 4;

    int hr[5], wr[5];
    #pragma unroll
    for (int d = 0; d < 5; d++) {
        hr[d] = refl(ph + d - 2);
        wr[d] = refl(pw + d - 2);
    }

    const float* __restrict__ xt = g_x2t + (size_t)n * HW * Cc;

    // Load this lane's 13 pixels (float4 of its channel group). All static
    // indices into hr/wr after unroll; k=25 (r=12,h=1) aliased to k=24,
    // its softmax weight is forced to 0 below.
    float4 a[13];
    #pragma unroll
    for (int r = 0; r < 13; r++) {
        const int kA = 2 * r;
        const int kB = (2 * r + 1 <= 24) ? (2 * r + 1) : 24;
        int offA = (hr[kA / 5] * Ww + wr[kA % 5]) * Cc;
        int offB = (hr[kB / 5] * Ww + wr[kB % 5]) * Cc;
        int off  = h ? offB : offA;
        a[r] = *(const float4*)(xt + off + cg);
    }

    // xp: lanes 0-15 load 4 scattered channels from x1, share to upper half.
    float4 xp = make_float4(0.f, 0.f, 0.f, 0.f);
    const size_t b0 = ((size_t)n * Cc + cg) * HW + (size_t)ph * Ww + pw;
    if (l < 16) {
        xp.x = x1[b0];
        xp.y = x1[b0 + HW];
        xp.z = x1[b0 + 2 * HW];
        xp.w = x1[b0 + 3 * HW];
    }
    xp.x += __shfl_xor_sync(0xffffffffu, xp.x, 16);
    xp.y += __shfl_xor_sync(0xffffffffu, xp.y, 16);
    xp.z += __shfl_xor_sync(0xffffffffu, xp.z, 16);
    xp.w += __shfl_xor_sync(0xffffffffu, xp.w, 16);

    // Energies: partial dot per lane, butterfly over the 16-lane half.
    float e[13], eo[13];
    #pragma unroll
    for (int r = 0; r < 13; r++) {
        float s = xp.x * a[r].x + xp.y * a[r].y + xp.z * a[r].z + xp.w * a[r].w;
        s += __shfl_xor_sync(0xffffffffu, s, 1);
        s += __shfl_xor_sync(0xffffffffu, s, 2);
        s += __shfl_xor_sync(0xffffffffu, s, 4);
        s += __shfl_xor_sync(0xffffffffu, s, 8);
        e[r] = s;                                     // e_{2r+h}
        eo[r] = __shfl_xor_sync(0xffffffffu, s, 16);  // e_{2r+(1-h)}
    }
    // k=25 doesn't exist: own slot 12 invalid on half 1, other slot 12 on half 0
    if (h) e[12] = -1e30f; else eo[12] = -1e30f;

    float m = -1e30f;
    #pragma unroll
    for (int r = 0; r < 13; r++) m = fmaxf(m, fmaxf(e[r], eo[r]));
    float sum = 0.f;
    #pragma unroll
    for (int r = 0; r < 13; r++) {
        e[r] = __expf(e[r] - m);
        sum += e[r] + __expf(eo[r] - m);
    }
    const float inv = 1.0f / sum;

    // Fusion over this lane's pixels, then combine the two halves.
    float4 f = make_float4(0.f, 0.f, 0.f, 0.f);
    #pragma unroll
    for (int r = 0; r < 13; r++) {
        float w = e[r] * inv;
        f.x += w * a[r].x;
        f.y += w * a[r].y;
        f.z += w * a[r].z;
        f.w += w * a[r].w;
    }
    f.x += __shfl_xor_sync(0xffffffffu, f.x, 16);
    f.y += __shfl_xor_sync(0xffffffffu, f.y, 16);
    f.z += __shfl_xor_sync(0xffffffffu, f.z, 16);
    f.w += __shfl_xor_sync(0xffffffffu, f.w, 16);

    if (l < 16) {
        const float al = alpha[0];
        out[b0]          = xp.x + al * f.x;
        out[b0 + HW]     = xp.y + al * f.y;
        out[b0 + 2 * HW] = xp.z + al * f.z;
        out[b0 + 3 * HW] = xp.w + al * f.w;
    }
}

// ---------------------------------------------------------------------------
// Kernel C: SFL passthrough (int -> float, output dtype) at buffer tail.
// ---------------------------------------------------------------------------
__global__ void sfl_copy_kernel(const int* __restrict__ SFL,
                                float* __restrict__ dst, int n_elems)
{
    int i = blockIdx.x * blockDim.x + threadIdx.x;
    if (i < n_elems) dst[i] = (float)SFL[i];
}

extern "C" void kernel_launch(void* const* d_in, const int* in_sizes, int n_in,
                              void* d_out, int out_size)
{
    const float* x1    = (const float*)d_in[0];
    const float* x2    = (const float*)d_in[1];
    const int*   SFL   = (const int*)d_in[2];
    const float* alpha = (const float*)d_in[3];
    float* out = (float*)d_out;

    dim3 gA(HW / 128, Cc / 32, Nn);
    prep_kernel<<<gA, 256>>>((const float4*)x1, (const float4*)x2, alpha,
                             (float4*)out);

    attn_kernel<<<(Nn * PTS) / 8, 256>>>(x1, (const int2*)SFL, alpha, out);

    const int nsfl = in_sizes[2];                 // Nn*PTS*2 elements
    float* dst = out + ((size_t)out_size - (size_t)nsfl);
    sfl_copy_kernel<<<(nsfl + 255) / 256, 256>>>(SFL, dst, nsfl);
}